// round 12
// baseline (speedup 1.0000x reference)
#include <cuda_runtime.h>

// DropBlock, single fused kernel, V4=16 in two batches:
//   1. front-batch 8 float4 x loads (fills DRAM pipe before any barrier)
//   2. stage u, bit-parallel separable 7x7 backward dilation, mask*scale
//      float4s into shared (reusing u's buffer)  [3 barriers]
//   3. issue batch-2's 8 loads, then consume batch 1 (overlap), then batch 2
// V4=16 -> 1568 CTAs: halves per-CTA prologue overhead (ALU was 20.5%);
// batch-2 loads keep the read stream alive during phase-6 stores.
// GAMMA = 0.1/49 * (56^2/50^2) = 0.00256 exactly.

#define H 56
#define W 56
#define HW 3136          // 56*56
#define HW4 784          // HW/4
#define GAMMA 0.00256f
#define THREADS 256
#define V4 16
#define V4_PER_CTA (THREADS * V4)   // 4096

__global__ void __launch_bounds__(THREADS) dropblock_fused(
    const float4* __restrict__ x, const float4* __restrict__ u4,
    float4* __restrict__ out) {
    // 12.5KB buffer reused: u floats (prologue) then mask float4s (epilogue)
    __shared__ __align__(16) float s_buf[HW];
    __shared__ unsigned long long rowd[H];
    __shared__ unsigned long long dil[H];
    __shared__ int pc[H];

    const int tid = threadIdx.x;
    const int base = blockIdx.x * V4_PER_CTA + tid;

    // ── 1. front-batch first 8 stream loads (before any barrier) ──
    float4 v[8];
    #pragma unroll
    for (int k = 0; k < 8; ++k)
        v[k] = __ldcs(&x[base + k * THREADS]);

    // ── 2. stage u into shared (784 float4, coalesced) ──
    float4* s_buf4 = reinterpret_cast<float4*>(s_buf);
    #pragma unroll
    for (int j = 0; j < 4; ++j) {
        const int i = tid + j * THREADS;
        if (i < HW4) s_buf4[i] = __ldg(&u4[i]);
    }
    __syncthreads();

    // ── 3. row-wise backward dilation (width 7) as bit ops ──
    if (tid < H) {
        unsigned long long s = 0ULL;
        #pragma unroll
        for (int w = 0; w < W; ++w)
            s |= (unsigned long long)(s_buf[tid * W + w] < GAMMA) << w;
        unsigned long long a = s | (s << 1);     // shifts {0,1}
        unsigned long long b = a | (a << 2);     // shifts {0..3}
        unsigned long long c = b | (b << 3);     // shifts {0..6}
        rowd[tid] = c & ((1ULL << W) - 1ULL);
    }
    __syncthreads();

    // ── 4. column-wise rolling OR over rows h-6..h + popcount ──
    if (tid < H) {
        const int h0 = tid - 6 < 0 ? 0 : tid - 6;
        unsigned long long d = 0ULL;
        for (int h = h0; h <= tid; ++h) d |= rowd[h];
        dil[tid] = d;
        pc[tid] = __popcll(d);
    }
    __syncthreads();

    // ── 5. scale (redundant per-thread sum) + mask float4s over dead u buf ──
    int tot = 0;
    #pragma unroll
    for (int h = 0; h < H; ++h) tot += pc[h];
    const float scale = (float)HW / (float)(HW - tot);
    #pragma unroll
    for (int j = 0; j < 4; ++j) {
        const int s4 = tid + j * THREADS;
        if (s4 < HW4) {
            const int h = s4 / 14;               // 14 float4 per row
            const int w0 = (s4 % 14) * 4;
            const unsigned long long bits = dil[h] >> w0;
            float4 mk;
            mk.x = (bits & 1ULL) ? 0.0f : scale;
            mk.y = (bits & 2ULL) ? 0.0f : scale;
            mk.z = (bits & 4ULL) ? 0.0f : scale;
            mk.w = (bits & 8ULL) ? 0.0f : scale;
            s_buf4[s4] = mk;
        }
    }
    __syncthreads();

    // ── 6. issue batch-2 loads, then consume batch 1 (overlapped), batch 2 ──
    float4 w[8];
    #pragma unroll
    for (int k = 0; k < 8; ++k)
        w[k] = __ldcs(&x[base + (8 + k) * THREADS]);

    int s4 = base % HW4;                         // incremental wrap
    #pragma unroll
    for (int k = 0; k < 8; ++k) {
        const float4 mk = s_buf4[s4];
        v[k].x *= mk.x; v[k].y *= mk.y; v[k].z *= mk.z; v[k].w *= mk.w;
        __stcs(&out[base + k * THREADS], v[k]);
        s4 += THREADS;
        if (s4 >= HW4) s4 -= HW4;
    }
    #pragma unroll
    for (int k = 0; k < 8; ++k) {
        const float4 mk = s_buf4[s4];
        w[k].x *= mk.x; w[k].y *= mk.y; w[k].z *= mk.z; w[k].w *= mk.w;
        __stcs(&out[base + (8 + k) * THREADS], w[k]);
        s4 += THREADS;
        if (s4 >= HW4) s4 -= HW4;
    }
}

extern "C" void kernel_launch(void* const* d_in, const int* in_sizes, int n_in,
                              void* d_out, int out_size) {
    const float* x = (const float*)d_in[0];   // (32,256,56,56) f32
    const float* u = (const float*)d_in[1];   // (56,56) f32

    // 6,422,528 float4 = 1568 CTAs * 256 thr * 16
    const int n4 = out_size / 4;
    dropblock_fused<<<n4 / V4_PER_CTA, THREADS>>>(
        (const float4*)x, (const float4*)u, (float4*)d_out);
}